// round 11
// baseline (speedup 1.0000x reference)
#include <cuda_runtime.h>

// Shapes (fixed):
//   p1: [6,256,256] f32   bank
//   p2: [131072,256] f32  table
//   p3: [6,1] i32         row ids into p2
//   p4: [1,256] i32       gather columns
//   p5: [6,1] i32         slot (c index) per batch
//   p6: [1,256] i32       scatter columns
//   p7: [6,256,256] f32   EMA state
//   p8: [12,6,256] f32    query features
// out1: [12,6,256] f32, out2: [6,256,256] f32 (concatenated in d_out)

#define B 6
#define S 256
#define D 256
#define A 12
#define ABD (A * B * D)  // 18432

// Role B (out1): one block per (b, 16-d chunk): 6*16 = 96 blocks (ids 0..95).
#define NB_B (B * 16)
// Role A (out2): 32c x 64d tiles: 8 * 6 * 4 = 192 blocks.
#define NB_A (8 * B * 4)

// Shared pool (floats):
//  role B: sB[256][20] (5120) | p8t[256][16] (4096, reused as partials) | g[16]
//  role A: sA[32][68] (2176) | gA[64]
#define POOL_FLOATS 9232

__global__ __launch_bounds__(256)
void fused_kernel(const float* __restrict__ p1,
                  const float* __restrict__ p2,
                  const int* __restrict__ p3,
                  const int* __restrict__ p4,
                  const int* __restrict__ p5,
                  const int* __restrict__ p6,
                  const float* __restrict__ p7,
                  const float* __restrict__ p8,
                  float* __restrict__ out1,
                  float* __restrict__ out2) {
    __shared__ __align__(16) float pool[POOL_FLOATS];
    const int id = blockIdx.x;
    const int t  = threadIdx.x;

    if (id < NB_B) {
        // ── Role B: out1, 256c x 16d tile ───────────────────────────────
        float* sB  = pool;               // [256][20] add tile (c stride 20)
        float* p8t = pool + 256 * 20;    // [256][16]: p8t[c*16+a]
        float* g   = pool + 256 * 20 + 256 * 16;   // [16]

        const int b    = id >> 4;
        const int d0   = (id & 15) * 16;
        const int slot = p5[b];

        // Stage p8 transposed: thread t handles c = t.
        #pragma unroll
        for (int a = 0; a < A; a++)
            p8t[t * 16 + a] = p8[(a * B + b) * 256 + t];
        if (t < 4)
            ((float4*)g)[t] = ((const float4*)(p1 + (b * S + slot) * D + d0))[t];
        __syncthreads();
        {
            int col = p6[t];
            if (col >= d0 && col < d0 + 16)
                g[col - d0] = p2[(long long)p3[b] * D + p4[t]];
        }
        __syncthreads();

        // Build add tile: thread = (f4 lane fl 0..3 over 16d, c-row cr 0..63).
        const float* p1b = p1 + b * (S * D);
        const float* p7b = p7 + b * (S * D);
        const int fl = t & 3, cr = t >> 2;
        #pragma unroll
        for (int i = 0; i < 4; i++) {
            int c = cr + 64 * i;
            float4 v1 = ((const float4*)(p1b + c * D + d0))[fl];
            float4 v7 = ((const float4*)(p7b + c * D + d0))[fl];
            float4 bs = (c == slot) ? ((const float4*)g)[fl] : v1;
            float4 val;
            val.x = fmaf(0.975f, v7.x, bs.x);
            val.y = fmaf(0.975f, v7.y, bs.y);
            val.z = fmaf(0.975f, v7.z, bs.z);
            val.w = fmaf(0.975f, v7.w, bs.w);
            *(float4*)(sB + c * 20 + fl * 4) = val;
        }
        __syncthreads();

        // GEMM: thread = (st 0..15, dp 0..7, h 0..1); c = j*16 + st.
        // 6 a's per thread (a = h*6+al), 6 float2 accumulators.
        const int st = t & 15;
        const int dp = (t >> 4) & 7;
        const int h  = t >> 7;
        float2 acc[6];
        #pragma unroll
        for (int al = 0; al < 6; al++) acc[al] = make_float2(0.f, 0.f);
        #pragma unroll
        for (int j = 0; j < 16; j++) {
            int c = j * 16 + st;
            float2 v   = *(const float2*)(sB + c * 20 + dp * 2);
            const float* w = p8t + c * 16 + h * 6;
            float2 w01 = *(const float2*)(w);
            float2 w23 = *(const float2*)(w + 2);
            float2 w45 = *(const float2*)(w + 4);
            acc[0].x = fmaf(w01.x, v.x, acc[0].x); acc[0].y = fmaf(w01.x, v.y, acc[0].y);
            acc[1].x = fmaf(w01.y, v.x, acc[1].x); acc[1].y = fmaf(w01.y, v.y, acc[1].y);
            acc[2].x = fmaf(w23.x, v.x, acc[2].x); acc[2].y = fmaf(w23.x, v.y, acc[2].y);
            acc[3].x = fmaf(w23.y, v.x, acc[3].x); acc[3].y = fmaf(w23.y, v.y, acc[3].y);
            acc[4].x = fmaf(w45.x, v.x, acc[4].x); acc[4].y = fmaf(w45.x, v.y, acc[4].y);
            acc[5].x = fmaf(w45.y, v.x, acc[5].x); acc[5].y = fmaf(w45.y, v.y, acc[5].y);
        }
        __syncthreads();                  // done reading p8t & sB

        // Partials: red2[(a*8 + dp)*16 + st], overlaid on p8t region.
        float2* red2 = (float2*)p8t;
        #pragma unroll
        for (int al = 0; al < 6; al++) {
            int a = h * 6 + al;
            red2[(a * 8 + dp) * 16 + st] = acc[al];
        }
        __syncthreads();

        // Combine 16 strips in fixed ascending order; 96 threads (a, dp).
        if (t < A * 8) {
            const float2* r = red2 + t * 16;
            float2 sum = r[0];
            #pragma unroll
            for (int q = 1; q < 16; q++) {
                float2 p = r[q];
                sum.x += p.x; sum.y += p.y;
            }
            int a = t >> 3, dpo = t & 7;
            *(float2*)(out1 + (a * B + b) * 256 + d0 + dpo * 2) = sum;
        }
        return;
    }

    // ── Role A: out2 via 32c x 64d transpose tile ───────────────────────
    float* sA = pool;            // [32][68]
    float* gA = pool + 32 * 68;  // [64], 16B-aligned (2176*4 % 16 == 0)

    const int k  = id - NB_B;
    const int d0 = (k & 3) * 64;
    const int b  = (k >> 2) % B;
    const int c0 = (k / (4 * B)) * 32;
    const int slot = p5[b];

    if (t < 16)
        ((float4*)gA)[t] = ((const float4*)(p1 + (b * S + slot) * D + d0))[t];
    __syncthreads();
    {
        int col = p6[t];
        if (col >= d0 && col < d0 + 64)
            gA[col - d0] = p2[(long long)p3[b] * D + p4[t]];
    }
    __syncthreads();

    const float* p1b = p1 + b * (S * D);
    const float* p7b = p7 + b * (S * D);
    float* out2b = out2 + b * (S * D);

    const int tx = t & 15;       // f4 d lane (64 d)
    const int ty = t >> 4;       // 16 c lanes, x2 iterations
    #pragma unroll
    for (int i = 0; i < 2; i++) {
        int cl = ty + 16 * i;
        int c  = c0 + cl;
        float4 v1 = ((const float4*)(p1b + c * D + d0))[tx];
        float4 v7 = ((const float4*)(p7b + c * D + d0))[tx];
        float4 bs = (c == slot) ? ((const float4*)gA)[tx] : v1;
        float4 val;
        val.x = fmaf(0.975f, v7.x, bs.x);
        val.y = fmaf(0.975f, v7.y, bs.y);
        val.z = fmaf(0.975f, v7.z, bs.z);
        val.w = fmaf(0.975f, v7.w, bs.w);
        ((float4*)(sA + cl * 68))[tx] = val;
    }
    __syncthreads();

    {
        int cl16 = t & 15;
        int dl0  = t >> 4;
        #pragma unroll
        for (int sub = 0; sub < 2; sub++) {
            #pragma unroll
            for (int p = 0; p < 4; p++) {
                int dl = dl0 + 16 * p;
                out2b[(d0 + dl) * D + c0 + sub * 16 + cl16] =
                    sA[(sub * 16 + cl16) * 68 + dl];
            }
        }
    }
}

extern "C" void kernel_launch(void* const* d_in, const int* in_sizes, int n_in,
                              void* d_out, int out_size) {
    const float* p1 = (const float*)d_in[0];
    const float* p2 = (const float*)d_in[1];
    const int*   p3 = (const int*)d_in[2];
    const int*   p4 = (const int*)d_in[3];
    const int*   p5 = (const int*)d_in[4];
    const int*   p6 = (const int*)d_in[5];
    const float* p7 = (const float*)d_in[6];
    const float* p8 = (const float*)d_in[7];

    float* out1 = (float*)d_out;                 // [12,6,256]
    float* out2 = out1 + ABD;                    // [6,256,256]

    fused_kernel<<<NB_A + NB_B, 256>>>(p1, p2, p3, p4, p5, p6, p7, p8, out1, out2);
}

// round 12
// speedup vs baseline: 1.1900x; 1.1900x over previous
#include <cuda_runtime.h>

// Shapes (fixed):
//   p1: [6,256,256] f32   bank
//   p2: [131072,256] f32  table
//   p3: [6,1] i32         row ids into p2
//   p4: [1,256] i32       gather columns
//   p5: [6,1] i32         slot (c index) per batch
//   p6: [1,256] i32       scatter columns
//   p7: [6,256,256] f32   EMA state
//   p8: [12,6,256] f32    query features
// out1: [12,6,256] f32, out2: [6,256,256] f32 (concatenated in d_out)

#define B 6
#define S 256
#define D 256
#define A 12
#define ABD (A * B * D)  // 18432

// Role B (out1): one block per (b, 32-d chunk): 6*8 = 48 blocks (ids 0..47).
#define NB_B (B * 8)
// Role A (out2): 32c x 64d tiles: 8 * 6 * 4 = 192 blocks.
#define NB_A (8 * B * 4)

// Shared pool (floats):
//  role B: sB[256][34] (8704) | p8s[12][256] (3072)  -> 11776 (47.1 KB)
//  role A: sA[32][68] (2176)
#define POOL_FLOATS 11776

__global__ __launch_bounds__(256)
void fused_kernel(const float* __restrict__ p1,
                  const float* __restrict__ p2,
                  const int* __restrict__ p3,
                  const int* __restrict__ p4,
                  const int* __restrict__ p5,
                  const int* __restrict__ p6,
                  const float* __restrict__ p7,
                  const float* __restrict__ p8,
                  float* __restrict__ out1,
                  float* __restrict__ out2) {
    __shared__ __align__(16) float pool[POOL_FLOATS];
    const int id = blockIdx.x;
    const int t  = threadIdx.x;

    if (id < NB_B) {
        // ── Role B: out1, 256c x 32d tile ───────────────────────────────
        float* sB  = pool;               // [256][34] add tile
        float* p8s = pool + 256 * 34;    // [12][256]

        const int b  = id >> 3;
        const int d0 = (id & 7) * 32;

        // Index prefetch + patch value (loads overlap the build pipeline).
        const int col  = p6[t];
        const int slot = p5[b];
        const bool hit = (col >= d0) && (col < d0 + 32);
        float patch = 0.f;
        if (hit)
            patch = p2[(long long)p3[b] * D + p4[t]]
                  + 0.975f * p7[(b * S + slot) * D + col];

        // Stage p8.
        #pragma unroll
        for (int i = 0; i < A; i++)
            p8s[i * 256 + t] = p8[(i * B + b) * 256 + t];

        // Build add tile, base = p1 always (slot handled by patch below).
        const float* p1b = p1 + b * (S * D);
        const float* p7b = p7 + b * (S * D);
        const int fl = t & 7, cr = t >> 3;
        #pragma unroll
        for (int i = 0; i < 8; i++) {
            int c = cr + 32 * i;
            float4 v1 = ((const float4*)(p1b + c * D + d0))[fl];
            float4 v7 = ((const float4*)(p7b + c * D + d0))[fl];
            float* row = sB + c * 34 + fl * 4;
            row[0] = fmaf(0.975f, v7.x, v1.x);
            row[1] = fmaf(0.975f, v7.y, v1.y);
            row[2] = fmaf(0.975f, v7.z, v1.z);
            row[3] = fmaf(0.975f, v7.w, v1.w);
        }
        __syncthreads();

        // Patch the scattered elements of the slot row.
        if (hit) sB[slot * 34 + (col - d0)] = patch;
        __syncthreads();

        // Micro-GEMM: 192 threads = (a, d-pair), 4 interleaved chains,
        // p8 as float4 per 4 c. Fixed order -> deterministic.
        if (t < A * 16) {
            const int a  = t >> 4;
            const int dp = t & 15;
            const float* pr = p8s + a * 256;
            const float* sc = sB + dp * 2;
            float ax0 = 0.f, ax1 = 0.f, ax2 = 0.f, ax3 = 0.f;
            float ay0 = 0.f, ay1 = 0.f, ay2 = 0.f, ay3 = 0.f;
            #pragma unroll 8
            for (int c = 0; c < 256; c += 4) {
                float4 w  = *(const float4*)(pr + c);
                float2 v0 = *(const float2*)(sc + (c + 0) * 34);
                float2 v1 = *(const float2*)(sc + (c + 1) * 34);
                float2 v2 = *(const float2*)(sc + (c + 2) * 34);
                float2 v3 = *(const float2*)(sc + (c + 3) * 34);
                ax0 = fmaf(w.x, v0.x, ax0); ay0 = fmaf(w.x, v0.y, ay0);
                ax1 = fmaf(w.y, v1.x, ax1); ay1 = fmaf(w.y, v1.y, ay1);
                ax2 = fmaf(w.z, v2.x, ax2); ay2 = fmaf(w.z, v2.y, ay2);
                ax3 = fmaf(w.w, v3.x, ax3); ay3 = fmaf(w.w, v3.y, ay3);
            }
            float sx = (ax0 + ax1) + (ax2 + ax3);
            float sy = (ay0 + ay1) + (ay2 + ay3);
            int base = (a * B + b) * 256 + d0 + dp * 2;
            *(float2*)(out1 + base) = make_float2(sx, sy);
        }
        return;
    }

    // ── Role A: out2 via 32c x 64d transpose tile ───────────────────────
    float* sA = pool;            // [32][68]

    const int k  = id - NB_B;
    const int d0 = (k & 3) * 64;
    const int b  = (k >> 2) % B;
    const int c0 = (k / (4 * B)) * 32;

    // Index prefetch + patch value (overlaps main loads).
    const int col  = p6[t];
    const int slot = p5[b];
    const bool hit = (col >= d0) && (col < d0 + 64) &&
                     (slot >= c0) && (slot < c0 + 32);
    float patch = 0.f;
    if (hit)
        patch = p2[(long long)p3[b] * D + p4[t]]
              + 0.975f * p7[(b * S + slot) * D + col];

    const float* p1b = p1 + b * (S * D);
    const float* p7b = p7 + b * (S * D);
    float* out2b = out2 + b * (S * D);

    const int tx = t & 15;       // f4 d lane (64 d)
    const int ty = t >> 4;       // 16 c lanes, x2 iterations
    #pragma unroll
    for (int i = 0; i < 2; i++) {
        int cl = ty + 16 * i;
        int c  = c0 + cl;
        float4 v1 = ((const float4*)(p1b + c * D + d0))[tx];
        float4 v7 = ((const float4*)(p7b + c * D + d0))[tx];
        float4 val;
        val.x = fmaf(0.975f, v7.x, v1.x);
        val.y = fmaf(0.975f, v7.y, v1.y);
        val.z = fmaf(0.975f, v7.z, v1.z);
        val.w = fmaf(0.975f, v7.w, v1.w);
        ((float4*)(sA + cl * 68))[tx] = val;
    }
    __syncthreads();

    if (hit) sA[(slot - c0) * 68 + (col - d0)] = patch;
    __syncthreads();

    {
        int cl16 = t & 15;
        int dl0  = t >> 4;
        #pragma unroll
        for (int sub = 0; sub < 2; sub++) {
            #pragma unroll
            for (int p = 0; p < 4; p++) {
                int dl = dl0 + 16 * p;
                out2b[(d0 + dl) * D + c0 + sub * 16 + cl16] =
                    sA[(sub * 16 + cl16) * 68 + dl];
            }
        }
    }
}

extern "C" void kernel_launch(void* const* d_in, const int* in_sizes, int n_in,
                              void* d_out, int out_size) {
    const float* p1 = (const float*)d_in[0];
    const float* p2 = (const float*)d_in[1];
    const int*   p3 = (const int*)d_in[2];
    const int*   p4 = (const int*)d_in[3];
    const int*   p5 = (const int*)d_in[4];
    const int*   p6 = (const int*)d_in[5];
    const float* p7 = (const float*)d_in[6];
    const float* p8 = (const float*)d_in[7];

    float* out1 = (float*)d_out;                 // [12,6,256]
    float* out2 = out1 + ABD;                    // [6,256,256]

    fused_kernel<<<NB_A + NB_B, 256>>>(p1, p2, p3, p4, p5, p6, p7, p8, out1, out2);
}

// round 13
// speedup vs baseline: 1.2969x; 1.0898x over previous
#include <cuda_runtime.h>

// Shapes (fixed):
//   p1: [6,256,256] f32   bank
//   p2: [131072,256] f32  table
//   p3: [6,1] i32         row ids into p2
//   p4: [1,256] i32       gather columns
//   p5: [6,1] i32         slot (c index) per batch
//   p6: [1,256] i32       scatter columns
//   p7: [6,256,256] f32   EMA state
//   p8: [12,6,256] f32    query features
// out1: [12,6,256] f32, out2: [6,256,256] f32 (concatenated in d_out)

#define B 6
#define S 256
#define D 256
#define A 12
#define ABD (A * B * D)  // 18432

#define DT 16                 // d per block strip
#define NBLK (B * (D / DT))   // 96 blocks
#define TPB 512
#define STRIDE 20             // sB row stride (floats): f4-aligned, conflict-free build

// Single-role kernel: one block per (b, 16-d strip). 512 threads.
//   tile sB[c][d] = p1 + 0.975*p7, then patch scattered slot-row elements.
//   out1[a,b,d0+dd] = sum_c p8[a,b,c] * sB[c][dd]   (c split across 2 groups)
//   out2[b,d0+dl,c] = sB[c][dl]                      (coalesced drain)
__global__ __launch_bounds__(TPB)
void fused_kernel(const float* __restrict__ p1,
                  const float* __restrict__ p2,
                  const int* __restrict__ p3,
                  const int* __restrict__ p4,
                  const int* __restrict__ p5,
                  const int* __restrict__ p6,
                  const float* __restrict__ p7,
                  const float* __restrict__ p8,
                  float* __restrict__ out1,
                  float* __restrict__ out2) {
    __shared__ __align__(16) float sB[256 * STRIDE];   // 20 KB add tile
    __shared__ __align__(16) float p8s[A * 256];       // 12 KB
    __shared__ float red[2 * A * DT];                  // 1.5 KB half-sums

    const int id = blockIdx.x;
    const int b  = id / (D / DT);
    const int d0 = (id % (D / DT)) * DT;
    const int t  = threadIdx.x;

    // Index prefetch + patch value (t<256; overlaps everything below).
    const int slot = p5[b];
    bool hit = false; int col = 0; float patch = 0.f;
    if (t < 256) {
        col = p6[t];
        hit = (col >= d0) && (col < d0 + DT);
        if (hit)
            patch = p2[(long long)p3[b] * D + p4[t]]
                  + 0.975f * p7[(b * S + slot) * D + col];
    }

    // Stage p8: 12*256 floats, 6 per thread, coalesced.
    #pragma unroll
    for (int i = 0; i < 6; i++) {
        int idx = t + TPB * i;
        p8s[idx] = p8[((idx >> 8) * B + b) * 256 + (idx & 255)];
    }

    // Build tile: thread = (f4 lane fl 0..3, c-row cr 0..127), 2 c-iters.
    const float* p1b = p1 + b * (S * D);
    const float* p7b = p7 + b * (S * D);
    const int fl = t & 3, cr = t >> 2;
    #pragma unroll
    for (int i = 0; i < 2; i++) {
        int c = cr + 128 * i;
        float4 v1 = ((const float4*)(p1b + c * D + d0))[fl];
        float4 v7 = ((const float4*)(p7b + c * D + d0))[fl];
        float4 val;
        val.x = fmaf(0.975f, v7.x, v1.x);
        val.y = fmaf(0.975f, v7.y, v1.y);
        val.z = fmaf(0.975f, v7.z, v1.z);
        val.w = fmaf(0.975f, v7.w, v1.w);
        *(float4*)(sB + c * STRIDE + fl * 4) = val;
    }
    __syncthreads();

    // Patch scattered elements of the slot row.
    if (hit) sB[slot * STRIDE + (col - d0)] = patch;
    __syncthreads();

    // GEMM: t<384. dd = t&15, g = t>>4 (0..23), a = g%12, h = g/12.
    // Warps 0-5: h=0 (c 0..127), warps 6-11: h=1 (c 128..255).
    if (t < 2 * A * DT) {
        const int dd = t & 15;
        const int g  = t >> 4;
        const int a  = g % A;
        const int h  = g / A;
        const float* pr = p8s + a * 256 + h * 128;
        const float* sc = sB + h * 128 * STRIDE + dd;
        float a0 = 0.f, a1 = 0.f, a2 = 0.f, a3 = 0.f;
        #pragma unroll 8
        for (int c = 0; c < 128; c += 4) {
            float4 w = *(const float4*)(pr + c);
            a0 = fmaf(w.x, sc[(c + 0) * STRIDE], a0);
            a1 = fmaf(w.y, sc[(c + 1) * STRIDE], a1);
            a2 = fmaf(w.z, sc[(c + 2) * STRIDE], a2);
            a3 = fmaf(w.w, sc[(c + 3) * STRIDE], a3);
        }
        red[h * (A * DT) + a * DT + dd] = (a0 + a1) + (a2 + a3);
    }
    __syncthreads();

    // Combine halves (fixed order) and write out1; drain out2 with all threads.
    if (t < A * DT) {
        float sum = red[t] + red[A * DT + t];
        int a = t >> 4, dd = t & 15;
        out1[(a * B + b) * 256 + d0 + dd] = sum;
    }

    float* out2b = out2 + b * (S * D);
    #pragma unroll
    for (int i = 0; i < 8; i++) {
        int idx = t + TPB * i;            // 4096 floats = 16 rows x 256
        int dl = idx >> 8, c = idx & 255;
        out2b[(d0 + dl) * D + c] = sB[c * STRIDE + dl];
    }
}

extern "C" void kernel_launch(void* const* d_in, const int* in_sizes, int n_in,
                              void* d_out, int out_size) {
    const float* p1 = (const float*)d_in[0];
    const float* p2 = (const float*)d_in[1];
    const int*   p3 = (const int*)d_in[2];
    const int*   p4 = (const int*)d_in[3];
    const int*   p5 = (const int*)d_in[4];
    const int*   p6 = (const int*)d_in[5];
    const float* p7 = (const float*)d_in[6];
    const float* p8 = (const float*)d_in[7];

    float* out1 = (float*)d_out;                 // [12,6,256]
    float* out2 = out1 + ABD;                    // [6,256,256]

    fused_kernel<<<NBLK, TPB>>>(p1, p2, p3, p4, p5, p6, p7, p8, out1, out2);
}